// round 14
// baseline (speedup 1.0000x reference)
#include <cuda_runtime.h>

#define NPTS  4096
#define NB    8
#define CDIM  32
#define KOUT  9
#define KALL  18
#define TILE  128
#define NTHREADS 256
#define CAP   32

// shared memory layout (float offsets)
#define SM_QT 0
#define SM_PT (SM_QT + CDIM*TILE)            // 4096   pt[2][32][128]
#define SM_DT (SM_PT + 2*CDIM*TILE)          // 12288
#define SM_RN (SM_DT + TILE*TILE)            // 28672
#define SM_CN (SM_RN + TILE)                 // 28800  cn[2][128]
#define SM_QH (SM_CN + 2*TILE)               // 29056
#define SM_BD (SM_QH + NTHREADS)             // 29312
#define SM_BI (SM_BD + CAP*NTHREADS)         // 37504
#define SMEM_FLOATS (SM_BI + (CAP*NTHREADS)/2)   // 41600
#define SMEM_BYTES  (SMEM_FLOATS * 4)        // 166,400 bytes

__device__ float g_sq[NB * NPTS];

__global__ void sqnorm_kernel(const float* __restrict__ x) {
    int idx = blockIdx.x * blockDim.x + threadIdx.x;
    if (idx >= NB * NPTS) return;
    int b = idx >> 12;
    int n = idx & (NPTS - 1);
    const float* p = x + (size_t)(b * CDIM) * NPTS + n;
    float s = 0.f;
#pragma unroll
    for (int c = 0; c < CDIM; c++) {
        float v = p[c * NPTS];
        s = fmaf(v, v, s);
    }
    g_sq[idx] = s;
}

__device__ __forceinline__ void ffma2(unsigned long long& acc,
                                      unsigned long long a,
                                      unsigned long long b) {
    asm("fma.rn.f32x2 %0, %1, %2, %0;" : "+l"(acc) : "l"(a), "l"(b));
}
__device__ __forceinline__ unsigned long long packdup(float v) {
    unsigned long long r;
    asm("mov.b64 %0, {%1, %1};" : "=l"(r) : "r"(__float_as_uint(v)));
    return r;
}
__device__ __forceinline__ void unpack2(unsigned long long v, float& lo, float& hi) {
    unsigned int a, b;
    asm("mov.b64 {%0, %1}, %2;" : "=r"(a), "=r"(b) : "l"(v));
    lo = __uint_as_float(a); hi = __uint_as_float(b);
}

// ---------------------------------------------------------------------------
// 128x128 tiles, 256 threads, 8x8 f32x2 fragments (LDS:FFMA2 = 0.125):
//  - compute: 16x16 grid; thread covers rows 8ty..8ty+7, cols 4tx..,64+4tx..
//    -> 4 LDS.128 per c-step for 32 FFMA2 (balanced LSU vs FMA pipe)
//  - warp w writes AND scans rows 16w..16w+15 -> __syncwarp only
//  - pt/cn double-buffered: one __syncthreads per tile
//  - scan: thread owns a HALF-row (64 cands); filter vs row bound
//    (min of the 2 half-18ths), lane-private push (CAP=32, in-order flush),
//    batch insert warp-max(cnt) times
//  - end: 2-way lexicographic (d, idx) merge per row == jax top_k order
// ---------------------------------------------------------------------------
__global__ __launch_bounds__(NTHREADS, 1)
void knn_kernel(const float* __restrict__ x, float* __restrict__ out) {
    extern __shared__ float sm[];
    float* qt = sm + SM_QT;
    float* ptb = sm + SM_PT;   // [2][32][128]
    float* dt = sm + SM_DT;
    float* rn = sm + SM_RN;
    float* cnb = sm + SM_CN;   // [2][128]
    float* qh = sm + SM_QH;
    float* bd = sm + SM_BD;
    short* bi = (short*)(sm + SM_BI);

    const int b    = blockIdx.y;
    const int row0 = blockIdx.x * TILE;
    const int tid  = threadIdx.x;
    const int tx   = tid & 15;
    const int ty   = tid >> 4;
    const float* xb = x + (size_t)(b * CDIM) * NPTS;

    const int srow = tid >> 1;          // scan row (0..127)
    const int half = tid & 1;           // half-row
    const int ssw  = srow & 31;

    float dl[KALL];
    int   il[KALL];
#pragma unroll
    for (int j = 0; j < KALL; j++) { dl[j] = 3.4e38f; il[j] = 0x7FFFFFFF; }

    auto insert = [&](float d, int mi) {
#pragma unroll
        for (int j = KALL - 1; j >= 1; j--) {
            bool sh = d < dl[j - 1];
            bool pl = !sh && (d < dl[j]);
            float pd = dl[j - 1]; int pi = il[j - 1];
            dl[j] = sh ? pd : (pl ? d  : dl[j]);
            il[j] = sh ? pi : (pl ? mi : il[j]);
        }
        if (d < dl[0]) { dl[0] = d; il[0] = mi; }
    };

#pragma unroll
    for (int k = 0; k < (CDIM * TILE) / NTHREADS; k++) {
        int idx = k * NTHREADS + tid;
        qt[idx] = xb[(idx >> 7) * NPTS + row0 + (idx & 127)];
    }
    if (tid < TILE) rn[tid] = g_sq[b * NPTS + row0 + tid];
    qh[tid] = 3.4e38f;
    // prologue: tile 0 into buffer 0
#pragma unroll
    for (int k = 0; k < (CDIM * TILE) / NTHREADS; k++) {
        int idx = k * NTHREADS + tid;
        ptb[idx] = xb[(idx >> 7) * NPTS + (idx & 127)];
    }
    if (tid < TILE) cnb[tid] = g_sq[b * NPTS + tid];
    __syncthreads();

    for (int t = 0; t < NPTS / TILE; t++) {
        const int cur = t & 1;
        float* pt = ptb + cur * CDIM * TILE;
        float* cn = cnb + cur * TILE;
        const int m0 = t * TILE;

        // issue next tile's loads (hidden behind compute)
        if (t < NPTS / TILE - 1) {
            float* ptn = ptb + (cur ^ 1) * CDIM * TILE;
            int m1 = m0 + TILE;
#pragma unroll
            for (int k = 0; k < (CDIM * TILE) / NTHREADS; k++) {
                int idx = k * NTHREADS + tid;
                ptn[idx] = xb[(idx >> 7) * NPTS + m1 + (idx & 127)];
            }
            if (tid < TILE) cnb[(cur ^ 1) * TILE + tid] = g_sq[b * NPTS + m1 + tid];
        }

        // ---- 128x128x32 inner products: 8 rows x 4 col-pairs of f32x2 ----
        unsigned long long acc2[8][4];
#pragma unroll
        for (int i = 0; i < 8; i++)
#pragma unroll
            for (int j = 0; j < 4; j++) acc2[i][j] = 0ull;

#pragma unroll 2
        for (int c = 0; c < CDIM; c++) {
            float4 qa = *(const float4*)(qt + c * TILE + 8 * ty);
            float4 qb = *(const float4*)(qt + c * TILE + 8 * ty + 4);
            ulonglong2 pA = *(const ulonglong2*)(pt + c * TILE + 4 * tx);
            ulonglong2 pB = *(const ulonglong2*)(pt + c * TILE + 64 + 4 * tx);
            unsigned long long qq[8] = {
                packdup(qa.x), packdup(qa.y), packdup(qa.z), packdup(qa.w),
                packdup(qb.x), packdup(qb.y), packdup(qb.z), packdup(qb.w)};
#pragma unroll
            for (int i = 0; i < 8; i++) {
                ffma2(acc2[i][0], qq[i], pA.x);
                ffma2(acc2[i][1], qq[i], pA.y);
                ffma2(acc2[i][2], qq[i], pB.x);
                ffma2(acc2[i][3], qq[i], pB.y);
            }
        }

        // ---- epilogue: d = (rn - 2*acc) + cn, swizzled float4 stores ----
        float cnv[8];
#pragma unroll
        for (int j = 0; j < 8; j++)
            cnv[j] = cn[(j < 4) ? (4 * tx + j) : (60 + 4 * tx + j)];

#pragma unroll
        for (int i = 0; i < 8; i++) {
            int r = 8 * ty + i;
            float rni = rn[r];
            float a0, a1, a2, a3, a4, a5, a6, a7;
            unpack2(acc2[i][0], a0, a1);
            unpack2(acc2[i][1], a2, a3);
            unpack2(acc2[i][2], a4, a5);
            unpack2(acc2[i][3], a6, a7);
            float4 v0, v1;
            v0.x = (rni - 2.f * a0) + cnv[0];
            v0.y = (rni - 2.f * a1) + cnv[1];
            v0.z = (rni - 2.f * a2) + cnv[2];
            v0.w = (rni - 2.f * a3) + cnv[3];
            v1.x = (rni - 2.f * a4) + cnv[4];
            v1.y = (rni - 2.f * a5) + cnv[5];
            v1.z = (rni - 2.f * a6) + cnv[6];
            v1.w = (rni - 2.f * a7) + cnv[7];
            int sw = r & 31;
            float4* dtr = (float4*)dt + r * 32;
            dtr[tx ^ sw]        = v0;
            dtr[(16 + tx) ^ sw] = v1;
        }
        __syncwarp();   // warp w's dt rows (16w..16w+15) are warp-private

        // ---- phase A: filter half-row vs row-shared bound ----
        {
            float tv = fminf(qh[tid & ~1], qh[tid | 1]);

            const float4* dtr = (const float4*)dt + srow * 32;
            int cnt = 0;
#pragma unroll
            for (int l = 0; l < 16; l++) {
                float4 v = dtr[(half * 16 + l) ^ ssw];
                int mb = m0 + half * 64 + 4 * l;
                float dv[4] = {v.x, v.y, v.z, v.w};
#pragma unroll
                for (int e = 0; e < 4; e++) {
                    float d = dv[e];
                    if (d <= tv) {
                        if (cnt == CAP) {   // in-order flush (tile 0 only)
                            for (int s = 0; s < CAP; s++)
                                insert(bd[s * NTHREADS + tid],
                                       (int)bi[s * NTHREADS + tid]);
                            cnt = 0;
                        }
                        bd[cnt * NTHREADS + tid] = d;
                        bi[cnt * NTHREADS + tid] = (short)(mb + e);
                        cnt++;
                    }
                }
            }

            // ---- phase B: batch insert, warp-max(cnt) network runs ----
            int nmax = __reduce_max_sync(0xFFFFFFFFu, cnt);
            for (int s = 0; s < nmax; s++) {
                float d  = 3.4e38f;
                int   mi = 0x7FFFFFFF;
                if (s < cnt) {
                    d  = bd[s * NTHREADS + tid];
                    mi = (int)bi[s * NTHREADS + tid];
                }
                insert(d, mi);   // +INF lanes are no-ops
            }
            qh[tid] = dl[KALL - 1];   // warp-private publish
        }
        __syncthreads();   // next-buffer loads visible; cur free to overwrite
    }

    // ---- dump half-row lists into dt region, then 2-way merge per row ----
    float* sd = dt;                       // 256*18 floats
    short* si = (short*)(dt + NTHREADS * KALL);
#pragma unroll
    for (int j = 0; j < KALL; j++) {
        sd[tid * KALL + j] = dl[j];
        si[tid * KALL + j] = (short)il[j];
    }
    __syncthreads();

    if (tid < TILE) {
        int c0 = 0, c1 = 0;
        int n = row0 + tid;
        int base0 = (b * NPTS + n) * KOUT;
        int base1 = ((NB + b) * NPTS + n) * KOUT;
        const float* sd0 = sd + (2 * tid) * KALL;
        const float* sd1 = sd + (2 * tid + 1) * KALL;
        const short* si0 = si + (2 * tid) * KALL;
        const short* si1 = si + (2 * tid + 1) * KALL;
#pragma unroll
        for (int t = 0; t < KALL; t++) {
            float d0 = sd0[c0], d1 = sd1[c1];
            int   i0 = (int)si0[c0], i1 = (int)si1[c1];
            bool take0 = (d0 < d1) || (d0 == d1 && i0 < i1);
            int biv = take0 ? i0 : i1;
            if (take0) c0++; else c1++;
            if ((t & 1) == 0) out[base0 + (t >> 1)] = (float)biv;
        }
#pragma unroll
        for (int j = 0; j < KOUT; j++) out[base1 + j] = (float)n;
    }
}

extern "C" void kernel_launch(void* const* d_in, const int* in_sizes, int n_in,
                              void* d_out, int out_size) {
    const float* x = (const float*)d_in[0];
    float* out = (float*)d_out;

    cudaFuncSetAttribute(knn_kernel, cudaFuncAttributeMaxDynamicSharedMemorySize,
                         SMEM_BYTES);

    sqnorm_kernel<<<(NB * NPTS + 255) / 256, 256>>>(x);

    dim3 grid(NPTS / TILE, NB);
    knn_kernel<<<grid, NTHREADS, SMEM_BYTES>>>(x, out);
}